// round 6
// baseline (speedup 1.0000x reference)
#include <cuda_runtime.h>
#include <cuda_fp16.h>
#include <cstdint>

#define NN 50000
#define EE 640000
#define CC 128
#define SCAN_B 512

// ---------------- device scratch (no allocations allowed) ----------------
__device__ __half   g_hsrc[NN * CC];   // h_src = in @ Ws   (fp16 gather table)
__device__ float    g_skip[NN * CC];   // skip  = in @ Wl   (fp32)
__device__ float    g_h   [NN * CC];   // layer-1 output
__device__ float    g_as  [NN];        // alpha_src per node
__device__ float    g_ad  [NN];        // alpha_dst per node
__device__ float    g_was1[CC], g_wad1[CC], g_was2[CC], g_wad2[CC];
// CSR (built once per launch; shared by both layers)
__device__ int      g_deg [NN];
__device__ int      g_off [NN + 1];
__device__ int      g_cur [NN];
__device__ int      g_bsum[128];
__device__ int      g_esrc[EE];        // src ids sorted by dst
__device__ int      g_edst[EE];        // dst ids in same order
__device__ float    g_ex  [EE];        // per-edge exp(logit), CSR order

// ---------------- combo (W@a vectors) + zero_deg merged ----------------
__global__ void combo_zero_kernel(const float* __restrict__ W1s, const float* __restrict__ a1s,
                                  const float* __restrict__ W1d, const float* __restrict__ a1d,
                                  const float* __restrict__ W2s, const float* __restrict__ a2s,
                                  const float* __restrict__ W2d, const float* __restrict__ a2d,
                                  int M) {
    int i = blockIdx.x * blockDim.x + threadIdx.x;
    if (i < M) g_deg[i] = 0;
    if (blockIdx.x == 0 && threadIdx.x < 128) {
        int k = threadIdx.x;
        float s1 = 0.f, d1 = 0.f, s2 = 0.f, d2 = 0.f;
        #pragma unroll 8
        for (int c = 0; c < CC; c++) {
            s1 += W1s[k * CC + c] * a1s[c];
            d1 += W1d[k * CC + c] * a1d[c];
            s2 += W2s[k * CC + c] * a2s[c];
            d2 += W2d[k * CC + c] * a2d[c];
        }
        g_was1[k] = s1; g_wad1[k] = d1; g_was2[k] = s2; g_wad2[k] = d2;
    }
}

// ---------------- CSR build ----------------
__global__ void hist_kernel(const int* __restrict__ dst, int E) {
    int e = blockIdx.x * blockDim.x + threadIdx.x;
    if (e < E) atomicAdd(&g_deg[dst[e]], 1);
}
__global__ __launch_bounds__(SCAN_B) void scan1_kernel(int M) {
    __shared__ int wsum[16];
    int tid = threadIdx.x, lane = tid & 31, wid = tid >> 5;
    int i = blockIdx.x * SCAN_B + tid;
    int v = (i < M) ? g_deg[i] : 0;
    int x = v;
    #pragma unroll
    for (int o = 1; o < 32; o <<= 1) {
        int t = __shfl_up_sync(0xFFFFFFFFu, x, o);
        if (lane >= o) x += t;
    }
    if (lane == 31) wsum[wid] = x;
    __syncthreads();
    if (wid == 0) {
        int s = (lane < 16) ? wsum[lane] : 0;
        #pragma unroll
        for (int o = 1; o < 16; o <<= 1) {
            int t = __shfl_up_sync(0xFFFFFFFFu, s, o);
            if (lane >= o) s += t;
        }
        if (lane < 16) wsum[lane] = s;
    }
    __syncthreads();
    int base = wid ? wsum[wid - 1] : 0;
    int incl = base + x;
    if (i < M) g_off[i] = incl - v;                 // local exclusive
    if (tid == SCAN_B - 1) g_bsum[blockIdx.x] = incl;
}
__global__ __launch_bounds__(128) void scan2_kernel(int B) {
    __shared__ int sm[128];
    int v = (threadIdx.x < B) ? g_bsum[threadIdx.x] : 0;
    sm[threadIdx.x] = v;
    __syncthreads();
    for (int o = 1; o < 128; o <<= 1) {
        int t = (threadIdx.x >= o) ? sm[threadIdx.x - o] : 0;
        __syncthreads();
        sm[threadIdx.x] += t;
        __syncthreads();
    }
    if (threadIdx.x < B) g_bsum[threadIdx.x] = sm[threadIdx.x] - v;  // exclusive
}
__global__ void scan3_kernel(int M, int E) {
    int i = blockIdx.x * blockDim.x + threadIdx.x;
    if (i < M) {
        int o = g_off[i] + g_bsum[i / SCAN_B];
        g_off[i] = o;
        g_cur[i] = o;
    }
    if (i == 0) g_off[M] = E;
}
__global__ void scatter_kernel(const int* __restrict__ src, const int* __restrict__ dst, int E) {
    int e = blockIdx.x * blockDim.x + threadIdx.x;
    if (e >= E) return;
    int d = dst[e];
    int pos = atomicAdd(&g_cur[d], 1);
    g_esrc[pos] = src[e];
    g_edst[pos] = d;
}

// ---------------- per-edge ex = exp(leaky(as[s]+ad[d])), CSR order ----------------
__global__ __launch_bounds__(256) void exf_kernel(int E) {
    int e = blockIdx.x * blockDim.x + threadIdx.x;
    if (e >= E) return;
    int s = g_esrc[e], d = g_edst[e];
    float v = __ldg(&g_as[s]) + __ldg(&g_ad[d]);
    v = v > 0.f ? v : 0.2f * v;   // LeakyReLU(0.2)
    g_ex[e] = __expf(v);
}

// ---------------- pipelined tf32 tensor-core SGEMM + fused alpha GEMV ----------------
// Double-buffered BK=32, 512 threads (16 warps), warp tile 32x32.
// y==0: C -> g_hsrc (fp16) + g_as/g_ad (fp32 gemv fused into load staging)
// y==1: C -> g_skip (fp32)
#define AST 36    // 32 + 4 pad
#define BST 136   // 128 + 8 pad
#define SMEM2 ((2 * 128 * AST + 2 * 32 * BST + 256) * 4)

__device__ __forceinline__ uint32_t f2tf32(float f) {
    uint32_t r;
    asm("cvt.rna.tf32.f32 %0, %1;" : "=r"(r) : "f"(f));
    return r;
}

__global__ __launch_bounds__(512) void sgemm_tf32_kernel(const float* __restrict__ A,
                                                         const float* __restrict__ B0,
                                                         const float* __restrict__ B1,
                                                         const float* __restrict__ was,
                                                         const float* __restrict__ wad,
                                                         int M) {
    extern __shared__ uint32_t sm[];
    uint32_t* AsBuf = sm;                          // [2][128][AST]
    uint32_t* BsBuf = sm + 2 * 128 * AST;          // [2][32][BST]
    float* sWas = (float*)(sm + 2 * 128 * AST + 2 * 32 * BST);
    float* sWad = sWas + 128;

    const float* B = (blockIdx.y == 0) ? B0 : B1;
    const int tid  = threadIdx.x;
    const int row0 = blockIdx.x * 128;

    if (tid < 128) { sWas[tid] = was[tid]; sWad[tid] = wad[tid]; }

    // staging coords (2 float4 slots each for A and B per buffer)
    const int ar0 = tid >> 3,          ac0 = (tid & 7) << 2;
    const int ar1 = (tid + 512) >> 3,  ac1 = ((tid + 512) & 7) << 2;
    const int brw0 = tid >> 5,         bc0 = (tid & 31) << 2;
    const int brw1 = brw0 + 16,        bc1 = bc0;

    const int gr0 = row0 + ar0, gr1 = row0 + ar1;

    float4 av0, av1, bv0, bv1;
    float s0 = 0.f, d0 = 0.f, s1 = 0.f, d1 = 0.f;   // gemv partials

    // ---- prologue: stage kb=0 ----
    av0 = (gr0 < M) ? *(const float4*)(A + (size_t)gr0 * 128 + ac0) : make_float4(0,0,0,0);
    av1 = (gr1 < M) ? *(const float4*)(A + (size_t)gr1 * 128 + ac1) : make_float4(0,0,0,0);
    bv0 = *(const float4*)(B + (size_t)brw0 * 128 + bc0);
    bv1 = *(const float4*)(B + (size_t)brw1 * 128 + bc1);
    {
        uint32_t* p = AsBuf + ar0 * AST + ac0 - 0;  // buffer 0, k-cols 0..31
        p[0] = f2tf32(av0.x); p[1] = f2tf32(av0.y); p[2] = f2tf32(av0.z); p[3] = f2tf32(av0.w);
        p = AsBuf + ar1 * AST + ac1;
        p[0] = f2tf32(av1.x); p[1] = f2tf32(av1.y); p[2] = f2tf32(av1.z); p[3] = f2tf32(av1.w);
        uint32_t* q = BsBuf + brw0 * BST + bc0;
        q[0] = f2tf32(bv0.x); q[1] = f2tf32(bv0.y); q[2] = f2tf32(bv0.z); q[3] = f2tf32(bv0.w);
        q = BsBuf + brw1 * BST + bc1;
        q[0] = f2tf32(bv1.x); q[1] = f2tf32(bv1.y); q[2] = f2tf32(bv1.z); q[3] = f2tf32(bv1.w);
    }
    __syncthreads();

    const int w      = tid >> 5;
    const int lane   = tid & 31;
    const int wr0    = (w >> 2) * 32;
    const int wn0    = (w & 3) * 32;
    const int grp    = lane >> 2;
    const int tig    = lane & 3;

    float acc[2][4][4];
    #pragma unroll
    for (int mt = 0; mt < 2; mt++)
        #pragma unroll
        for (int nt = 0; nt < 4; nt++)
            #pragma unroll
            for (int r = 0; r < 4; r++) acc[mt][nt][r] = 0.f;

    #pragma unroll
    for (int kb = 0; kb < 4; kb++) {
        // gemv partials from this stage's A regs (fp32), using smem was/wad
        {
            float4 w0s = *(const float4*)(sWas + kb * 32 + ac0);
            float4 w0d = *(const float4*)(sWad + kb * 32 + ac0);
            float4 w1s = *(const float4*)(sWas + kb * 32 + ac1);
            float4 w1d = *(const float4*)(sWad + kb * 32 + ac1);
            s0 += av0.x * w0s.x + av0.y * w0s.y + av0.z * w0s.z + av0.w * w0s.w;
            d0 += av0.x * w0d.x + av0.y * w0d.y + av0.z * w0d.z + av0.w * w0d.w;
            s1 += av1.x * w1s.x + av1.y * w1s.y + av1.z * w1s.z + av1.w * w1s.w;
            d1 += av1.x * w1d.x + av1.y * w1d.y + av1.z * w1d.z + av1.w * w1d.w;
        }
        // issue LDG for next stage early
        if (kb < 3) {
            int kc = (kb + 1) * 32;
            av0 = (gr0 < M) ? *(const float4*)(A + (size_t)gr0 * 128 + kc + ac0) : make_float4(0,0,0,0);
            av1 = (gr1 < M) ? *(const float4*)(A + (size_t)gr1 * 128 + kc + ac1) : make_float4(0,0,0,0);
            bv0 = *(const float4*)(B + (size_t)(kc + brw0) * 128 + bc0);
            bv1 = *(const float4*)(B + (size_t)(kc + brw1) * 128 + bc1);
        }
        // compute from buf[kb&1]
        const uint32_t* Asb = AsBuf + (kb & 1) * 128 * AST;
        const uint32_t* Bsb = BsBuf + (kb & 1) * 32 * BST;
        #pragma unroll
        for (int ks = 0; ks < 4; ks++) {
            int k0 = ks * 8;
            uint32_t a[2][4];
            #pragma unroll
            for (int mt = 0; mt < 2; mt++) {
                const uint32_t* p = Asb + (wr0 + mt * 16 + grp) * AST + k0 + tig;
                a[mt][0] = p[0];
                a[mt][1] = p[8 * AST];
                a[mt][2] = p[4];
                a[mt][3] = p[8 * AST + 4];
            }
            uint32_t b[4][2];
            #pragma unroll
            for (int nt = 0; nt < 4; nt++) {
                const uint32_t* p = Bsb + (k0 + tig) * BST + wn0 + nt * 8 + grp;
                b[nt][0] = p[0];
                b[nt][1] = p[4 * BST];
            }
            #pragma unroll
            for (int mt = 0; mt < 2; mt++)
                #pragma unroll
                for (int nt = 0; nt < 4; nt++) {
                    float* dd = acc[mt][nt];
                    asm volatile(
                        "mma.sync.aligned.m16n8k8.row.col.f32.tf32.tf32.f32 "
                        "{%0,%1,%2,%3}, {%4,%5,%6,%7}, {%8,%9}, {%0,%1,%2,%3};"
                        : "+f"(dd[0]), "+f"(dd[1]), "+f"(dd[2]), "+f"(dd[3])
                        : "r"(a[mt][0]), "r"(a[mt][1]), "r"(a[mt][2]), "r"(a[mt][3]),
                          "r"(b[nt][0]), "r"(b[nt][1]));
                }
        }
        // store next stage into the other buffer, then sync
        if (kb < 3) {
            uint32_t* Asn = AsBuf + ((kb + 1) & 1) * 128 * AST;
            uint32_t* Bsn = BsBuf + ((kb + 1) & 1) * 32 * BST;
            uint32_t* p = Asn + ar0 * AST + ac0;
            p[0] = f2tf32(av0.x); p[1] = f2tf32(av0.y); p[2] = f2tf32(av0.z); p[3] = f2tf32(av0.w);
            p = Asn + ar1 * AST + ac1;
            p[0] = f2tf32(av1.x); p[1] = f2tf32(av1.y); p[2] = f2tf32(av1.z); p[3] = f2tf32(av1.w);
            uint32_t* q = Bsn + brw0 * BST + bc0;
            q[0] = f2tf32(bv0.x); q[1] = f2tf32(bv0.y); q[2] = f2tf32(bv0.z); q[3] = f2tf32(bv0.w);
            q = Bsn + brw1 * BST + bc1;
            q[0] = f2tf32(bv1.x); q[1] = f2tf32(bv1.y); q[2] = f2tf32(bv1.z); q[3] = f2tf32(bv1.w);
            __syncthreads();
        }
    }

    if (blockIdx.y == 0) {
        // ---- gemv reduce within 8-lane groups (same A row) and write ----
        #pragma unroll
        for (int o = 4; o; o >>= 1) {
            s0 += __shfl_xor_sync(0xFFFFFFFFu, s0, o);
            d0 += __shfl_xor_sync(0xFFFFFFFFu, d0, o);
            s1 += __shfl_xor_sync(0xFFFFFFFFu, s1, o);
            d1 += __shfl_xor_sync(0xFFFFFFFFu, d1, o);
        }
        if ((lane & 7) == 0) {
            if (gr0 < M) { g_as[gr0] = s0; g_ad[gr0] = d0; }
            if (gr1 < M) { g_as[gr1] = s1; g_ad[gr1] = d1; }
        }
        // ---- fp16 epilogue -> g_hsrc ----
        #pragma unroll
        for (int mt = 0; mt < 2; mt++) {
            int r_lo = row0 + wr0 + mt * 16 + grp;
            int r_hi = r_lo + 8;
            #pragma unroll
            for (int nt = 0; nt < 4; nt++) {
                int col = wn0 + nt * 8 + tig * 2;
                if (r_lo < M)
                    *(__half2*)(g_hsrc + (size_t)r_lo * 128 + col) =
                        __float22half2_rn(make_float2(acc[mt][nt][0], acc[mt][nt][1]));
                if (r_hi < M)
                    *(__half2*)(g_hsrc + (size_t)r_hi * 128 + col) =
                        __float22half2_rn(make_float2(acc[mt][nt][2], acc[mt][nt][3]));
            }
        }
    } else {
        #pragma unroll
        for (int mt = 0; mt < 2; mt++) {
            int r_lo = row0 + wr0 + mt * 16 + grp;
            int r_hi = r_lo + 8;
            #pragma unroll
            for (int nt = 0; nt < 4; nt++) {
                int col = wn0 + nt * 8 + tig * 2;
                if (r_lo < M)
                    *(float2*)(g_skip + (size_t)r_lo * 128 + col) =
                        make_float2(acc[mt][nt][0], acc[mt][nt][1]);
                if (r_hi < M)
                    *(float2*)(g_skip + (size_t)r_hi * 128 + col) =
                        make_float2(acc[mt][nt][2], acc[mt][nt][3]);
            }
        }
    }
}

// ---------------- fused aggregation + epilogue (warp/node, no shuffles) ----------------
__global__ __launch_bounds__(256) void agg_kernel(const float* __restrict__ b,
                                                  const float* __restrict__ bl,
                                                  float* __restrict__ out_ext,
                                                  int relu_to_gh, int M) {
    int d = (blockIdx.x * blockDim.x + threadIdx.x) >> 5;
    int lane = threadIdx.x & 31;
    if (d >= M) return;

    int o0 = g_off[d], o1 = g_off[d + 1];

    float4 acc = make_float4(0.f, 0.f, 0.f, 0.f);
    float Sp = 0.f;
    const __half* __restrict__ H = g_hsrc;

    int j = o0;
    for (; j + 8 <= o1; j += 8) {
        int   s_[8];
        float e_[8];
        #pragma unroll
        for (int u = 0; u < 8; u++) {
            s_[u] = __ldg(&g_esrc[j + u]);   // warp-uniform broadcast
            e_[u] = __ldg(&g_ex[j + u]);
        }
        Sp += (e_[0] + e_[1]) + (e_[2] + e_[3]) + (e_[4] + e_[5]) + (e_[6] + e_[7]);
        uint2 u_[8];
        #pragma unroll
        for (int u = 0; u < 8; u++)
            u_[u] = *(const uint2*)(H + (size_t)s_[u] * 128 + lane * 4);
        #pragma unroll
        for (int u = 0; u < 8; u++) {
            float2 fa = __half22float2(*(__half2*)&u_[u].x);
            float2 fb = __half22float2(*(__half2*)&u_[u].y);
            acc.x += e_[u] * fa.x; acc.y += e_[u] * fa.y;
            acc.z += e_[u] * fb.x; acc.w += e_[u] * fb.y;
        }
    }
    for (; j < o1; j++) {
        int   s  = __ldg(&g_esrc[j]);
        float ex = __ldg(&g_ex[j]);
        Sp += ex;
        uint2 u = *(const uint2*)(H + (size_t)s * 128 + lane * 4);
        float2 fa = __half22float2(*(__half2*)&u.x);
        float2 fb = __half22float2(*(__half2*)&u.y);
        acc.x += ex * fa.x; acc.y += ex * fa.y;
        acc.z += ex * fb.x; acc.w += ex * fb.y;
    }

    float inv = 1.f / (Sp + 1e-16f);

    float4 sk  = *(const float4*)(g_skip + (size_t)d * 128 + lane * 4);
    float4 bb  = *(const float4*)(b + lane * 4);
    float4 bb2 = *(const float4*)(bl + lane * 4);

    float4 o;
    o.x = acc.x * inv + bb.x + sk.x + bb2.x;
    o.y = acc.y * inv + bb.y + sk.y + bb2.y;
    o.z = acc.z * inv + bb.z + sk.z + bb2.z;
    o.w = acc.w * inv + bb.w + sk.w + bb2.w;

    if (relu_to_gh) {
        o.x = fmaxf(o.x, 0.f); o.y = fmaxf(o.y, 0.f);
        o.z = fmaxf(o.z, 0.f); o.w = fmaxf(o.w, 0.f);
        *(float4*)(g_h + (size_t)d * 128 + lane * 4) = o;
    } else {
        *(float4*)(out_ext + (size_t)d * 128 + lane * 4) = o;
    }
}

// ---------------- launch ----------------
extern "C" void kernel_launch(void* const* d_in, const int* in_sizes, int n_in,
                              void* d_out, int out_size) {
    const float* x   = (const float*)d_in[0];
    const int*   ei  = (const int*)  d_in[1];
    const float* W1s = (const float*)d_in[2];
    const float* W1d = (const float*)d_in[3];
    const float* a1s = (const float*)d_in[4];
    const float* a1d = (const float*)d_in[5];
    const float* b1  = (const float*)d_in[6];
    const float* Wl1 = (const float*)d_in[7];
    const float* bl1 = (const float*)d_in[8];
    const float* W2s = (const float*)d_in[9];
    const float* W2d = (const float*)d_in[10];
    const float* a2s = (const float*)d_in[11];
    const float* a2d = (const float*)d_in[12];
    const float* b2  = (const float*)d_in[13];
    const float* Wl2 = (const float*)d_in[14];
    const float* bl2 = (const float*)d_in[15];

    const int M = in_sizes[0] / CC;        // 50000
    const int E = in_sizes[1] / 2;         // 640000
    const int* src = ei;
    const int* dst = ei + E;

    float *p_h = nullptr, *p_was1 = nullptr, *p_wad1 = nullptr,
          *p_was2 = nullptr, *p_wad2 = nullptr;
    cudaGetSymbolAddress((void**)&p_h,    g_h);     // queries only, capture-safe
    cudaGetSymbolAddress((void**)&p_was1, g_was1);
    cudaGetSymbolAddress((void**)&p_wad1, g_wad1);
    cudaGetSymbolAddress((void**)&p_was2, g_was2);
    cudaGetSymbolAddress((void**)&p_wad2, g_wad2);

    static bool attr_set = false;
    if (!attr_set) {
        cudaFuncSetAttribute(sgemm_tf32_kernel,
                             cudaFuncAttributeMaxDynamicSharedMemorySize, SMEM2);
        attr_set = true;
    }

    const int nodeBlocks  = (M + 255) / 256;
    const int edgeBlocks  = (E + 255) / 256;
    const int warpBlocks  = (int)(((long long)M * 32 + 255) / 256);
    const int scanBlocks  = (M + SCAN_B - 1) / SCAN_B;
    const dim3 gemmGrid((M + 127) / 128, 2);

    combo_zero_kernel<<<nodeBlocks, 256>>>(W1s, a1s, W1d, a1d, W2s, a2s, W2d, a2d, M);  // 1
    hist_kernel<<<edgeBlocks, 256>>>(dst, E);                                           // 2
    scan1_kernel<<<scanBlocks, SCAN_B>>>(M);                                            // 3
    sgemm_tf32_kernel<<<gemmGrid, 512, SMEM2>>>(x, W1s, Wl1, p_was1, p_wad1, M);        // 4 (ncu window)
    scan2_kernel<<<1, 128>>>(scanBlocks);                                               // 5
    scan3_kernel<<<nodeBlocks, 256>>>(M, E);                                            // 6
    scatter_kernel<<<edgeBlocks, 256>>>(src, dst, E);                                   // 7

    // ---- layer 1 ----
    exf_kernel<<<edgeBlocks, 256>>>(E);                                                 // 8
    agg_kernel<<<warpBlocks, 256>>>(b1, bl1, nullptr, 1, M);                            // 9

    // ---- layer 2 ----
    sgemm_tf32_kernel<<<gemmGrid, 512, SMEM2>>>(p_h, W2s, Wl2, p_was2, p_wad2, M);      // 10
    exf_kernel<<<edgeBlocks, 256>>>(E);                                                 // 11
    agg_kernel<<<warpBlocks, 256>>>(b2, bl2, (float*)d_out, 0, M);                      // 12
}